// round 2
// baseline (speedup 1.0000x reference)
#include <cuda_runtime.h>
#include <math.h>

#define Bq 4
#define Lq 4096
#define Dq 1024
#define Mq (Bq*Lq)              // 16384 rows
#define CHUNK 128
#define NCHUNK (Lq/CHUNK)       // 32

// ---------------- scratch (static device allocations) ----------------
__device__ float g_xn[(size_t)Mq*Dq];       // rmsnorm output (reused 3x)
__device__ float g_y [(size_t)Mq*Dq];       // dwconv output
__device__ float g_x1[(size_t)Mq*Dq];       // after conv block residual
__device__ float g_x2[(size_t)Mq*Dq];       // after gru residual
__device__ float g_c [(size_t)Mq*Dq];       // scan coeffs
__device__ float g_v [(size_t)Mq*Dq];       // scan values
__device__ float g_hg[(size_t)Mq*2*Dq];     // gru pre-activations
__device__ float g_h4[(size_t)Mq*4*Dq];     // ff intermediate
__device__ float g_Hc[Bq*NCHUNK*Dq];        // per-chunk scan value
__device__ float g_Cc[Bq*NCHUNK*Dq];        // per-chunk coeff product
__device__ float g_Hi[Bq*NCHUNK*Dq];        // per-chunk initial h

// ---------------- rmsnorm: one block per row, 256 thr x 4 elems ----------------
__global__ __launch_bounds__(256) void rmsnorm_k(const float* __restrict__ x,
                                                 const float* __restrict__ g,
                                                 float* __restrict__ out)
{
    const int row = blockIdx.x;
    const int tid = threadIdx.x;
    const float4* xr = (const float4*)(x + (size_t)row * Dq);
    float4 xv = xr[tid];
    float s = xv.x*xv.x + xv.y*xv.y + xv.z*xv.z + xv.w*xv.w;
    #pragma unroll
    for (int o = 16; o > 0; o >>= 1) s += __shfl_xor_sync(0xffffffffu, s, o);
    __shared__ float red[8];
    if ((tid & 31) == 0) red[tid >> 5] = s;
    __syncthreads();
    if (tid < 32) {
        float t2 = (tid < 8) ? red[tid] : 0.f;
        #pragma unroll
        for (int o = 4; o > 0; o >>= 1) t2 += __shfl_xor_sync(0xffffffffu, t2, o);
        if (tid == 0) red[0] = t2;
    }
    __syncthreads();
    float inv = 32.0f / fmaxf(sqrtf(red[0]), 1e-12f);   // sqrt(1024)=32
    const float4 gv = ((const float4*)g)[tid];
    float4 o4;
    o4.x = xv.x * inv * (gv.x + 1.f);
    o4.y = xv.y * inv * (gv.y + 1.f);
    o4.z = xv.z * inv * (gv.z + 1.f);
    o4.w = xv.w * inv * (gv.w + 1.f);
    ((float4*)(out + (size_t)row * Dq))[tid] = o4;
}

// ---------------- causal depthwise conv (K=3) + bias ----------------
__global__ __launch_bounds__(256) void dwconv_k(const float* __restrict__ wdw,
                                                const float* __restrict__ bdw)
{
    size_t idx = (size_t)blockIdx.x * 256 + threadIdx.x;   // over Mq*Dq
    int d = (int)(idx % Dq);
    size_t row = idx / Dq;
    int l = (int)(row % Lq);
    float w0 = wdw[d*3+0], w1 = wdw[d*3+1], w2 = wdw[d*3+2];
    float acc = bdw[d] + w2 * g_xn[idx];
    if (l >= 1) acc += w1 * g_xn[idx - Dq];
    if (l >= 2) acc += w0 * g_xn[idx - 2*Dq];
    g_y[idx] = acc;
}

// ---------------- generic NT GEMM: C[M,N] = A[M,K]*B[N,K]^T, epilogue per MODE
// MODE 0: +bias +res       (conv pointwise, residual x)
// MODE 1: plain            (gru pre-activations)
// MODE 2: +bias, exact gelu (ff1)
// MODE 3: +bias +res       (ff2, residual x2, writes final output)
template<int MODE>
__global__ __launch_bounds__(256) void gemm_nt(
    const float* __restrict__ A, const float* __restrict__ Bm,
    const float* __restrict__ bias, const float* __restrict__ res,
    float* __restrict__ C, int N_, int K_)
{
    __shared__ float As[8][128];
    __shared__ float Bs[8][128];
    const int tid = threadIdx.x;
    const int bm = blockIdx.y * 128;
    const int bn = blockIdx.x * 128;
    const int lr = tid >> 1;            // 0..127
    const int lc = (tid & 1) << 2;      // 0 or 4
    const float* Ag = A  + (size_t)(bm + lr) * K_ + lc;
    const float* Bg = Bm + (size_t)(bn + lr) * K_ + lc;
    const int tx = tid & 15;
    const int ty = tid >> 4;
    float acc[8][8];
    #pragma unroll
    for (int i = 0; i < 8; i++)
        #pragma unroll
        for (int j = 0; j < 8; j++) acc[i][j] = 0.f;

    for (int k0 = 0; k0 < K_; k0 += 8) {
        float4 a4 = *(const float4*)(Ag + k0);
        float4 b4 = *(const float4*)(Bg + k0);
        __syncthreads();
        As[lc+0][lr] = a4.x; As[lc+1][lr] = a4.y; As[lc+2][lr] = a4.z; As[lc+3][lr] = a4.w;
        Bs[lc+0][lr] = b4.x; Bs[lc+1][lr] = b4.y; Bs[lc+2][lr] = b4.z; Bs[lc+3][lr] = b4.w;
        __syncthreads();
        #pragma unroll
        for (int k = 0; k < 8; k++) {
            float ar[8], br[8];
            #pragma unroll
            for (int i = 0; i < 8; i++) ar[i] = As[k][ty*8 + i];
            #pragma unroll
            for (int j = 0; j < 8; j++) br[j] = Bs[k][tx*8 + j];
            #pragma unroll
            for (int i = 0; i < 8; i++)
                #pragma unroll
                for (int j = 0; j < 8; j++)
                    acc[i][j] = fmaf(ar[i], br[j], acc[i][j]);
        }
    }
    #pragma unroll
    for (int i = 0; i < 8; i++) {
        int row = bm + ty*8 + i;
        size_t coff = (size_t)row * N_ + bn + tx*8;
        #pragma unroll
        for (int jj = 0; jj < 8; jj += 4) {
            float vv[4];
            #pragma unroll
            for (int j = 0; j < 4; j++) {
                int col = bn + tx*8 + jj + j;
                float val = acc[i][jj+j];
                if (MODE == 0 || MODE == 3) {
                    val += bias[col] + res[(size_t)row * N_ + col];
                } else if (MODE == 2) {
                    val += bias[col];
                    val = 0.5f * val * (1.f + erff(val * 0.70710678118654752f));
                }
                vv[j] = val;
            }
            float4 o4 = make_float4(vv[0], vv[1], vv[2], vv[3]);
            *(float4*)(C + coff + jj) = o4;
        }
    }
}

// ---------------- minGRU chunked scan ----------------
// h_t = c_t * h_{t-1} + v_t  with  c = exp(-softplus(g)),
// v = exp(g - softplus(g) + log_g(hd)),  log_g(x) = x>=0 ? log(x+0.5) : x - log1p(e^x)
__global__ __launch_bounds__(256) void scan1_k(const float* __restrict__ hg)
{
    int d  = blockIdx.x * 256 + threadIdx.x;
    int ch = blockIdx.y;
    int b  = blockIdx.z;
    size_t row0 = (size_t)b * Lq + (size_t)ch * CHUNK;
    float h = 0.f, cp = 1.f;
    for (int t = 0; t < CHUNK; t++) {
        size_t r = row0 + t;
        float hd = hg[r*2*Dq + d];
        float gg = hg[r*2*Dq + Dq + d];
        float sp = fmaxf(gg, 0.f) + log1pf(expf(-fabsf(gg)));       // softplus(g)
        float lg = (hd >= 0.f) ? logf(hd + 0.5f) : (hd - log1pf(expf(hd)));
        float c = expf(-sp);
        float v = expf(gg - sp + lg);
        g_c[r*Dq + d] = c;
        g_v[r*Dq + d] = v;
        h = fmaf(c, h, v);
        cp *= c;
    }
    int sidx = (b*NCHUNK + ch)*Dq + d;
    g_Hc[sidx] = h;
    g_Cc[sidx] = cp;
}

__global__ __launch_bounds__(256) void scan2_k()
{
    int d = blockIdx.x * 256 + threadIdx.x;
    int b = blockIdx.z;
    float h = 0.f;
    for (int ch = 0; ch < NCHUNK; ch++) {
        int sidx = (b*NCHUNK + ch)*Dq + d;
        g_Hi[sidx] = h;
        h = fmaf(g_Cc[sidx], h, g_Hc[sidx]);
    }
}

__global__ __launch_bounds__(256) void scan3_k(const float* __restrict__ x1,
                                               float* __restrict__ x2,
                                               float* __restrict__ nh)
{
    int d  = blockIdx.x * 256 + threadIdx.x;
    int ch = blockIdx.y;
    int b  = blockIdx.z;
    size_t row0 = (size_t)b * Lq + (size_t)ch * CHUNK;
    float h = g_Hi[(b*NCHUNK + ch)*Dq + d];
    for (int t = 0; t < CHUNK; t++) {
        size_t r = row0 + t;
        h = fmaf(g_c[r*Dq + d], h, g_v[r*Dq + d]);
        x2[r*Dq + d] = h + x1[r*Dq + d];          // RES_SCALE = 1
    }
    if (ch == NCHUNK - 1) nh[b*Dq + d] = h;       // next_hidden (raw gru out)
}

// ---------------- launch ----------------
extern "C" void kernel_launch(void* const* d_in, const int* in_sizes, int n_in,
                              void* d_out, int out_size)
{
    const float* x           = (const float*)d_in[0];
    const float* conv_dw_w   = (const float*)d_in[1];
    const float* conv_dw_b   = (const float*)d_in[2];
    const float* conv_pw_w   = (const float*)d_in[3];
    const float* conv_pw_b   = (const float*)d_in[4];
    const float* conv_norm_g = (const float*)d_in[5];
    const float* gru_norm_g  = (const float*)d_in[6];
    const float* gru_w       = (const float*)d_in[7];
    const float* ff_norm_g   = (const float*)d_in[8];
    const float* ff_w1       = (const float*)d_in[9];
    const float* ff_b1       = (const float*)d_in[10];
    const float* ff_w2       = (const float*)d_in[11];
    const float* ff_b2       = (const float*)d_in[12];
    float* out = (float*)d_out;

    float *xn, *y, *x1, *x2, *hg, *h4;
    cudaGetSymbolAddress((void**)&xn, g_xn);
    cudaGetSymbolAddress((void**)&y,  g_y);
    cudaGetSymbolAddress((void**)&x1, g_x1);
    cudaGetSymbolAddress((void**)&x2, g_x2);
    cudaGetSymbolAddress((void**)&hg, g_hg);
    cudaGetSymbolAddress((void**)&h4, g_h4);

    // 1) conv block
    rmsnorm_k<<<Mq, 256>>>(x, conv_norm_g, xn);
    dwconv_k<<<(Mq*(size_t)Dq)/256, 256>>>(conv_dw_w, conv_dw_b);
    gemm_nt<0><<<dim3(Dq/128, Mq/128), 256>>>(y, conv_pw_w, conv_pw_b, x, x1, Dq, Dq);

    // 2) gru block
    rmsnorm_k<<<Mq, 256>>>(x1, gru_norm_g, xn);
    gemm_nt<1><<<dim3(2*Dq/128, Mq/128), 256>>>(xn, gru_w, nullptr, nullptr, hg, 2*Dq, Dq);
    scan1_k<<<dim3(Dq/256, NCHUNK, Bq), 256>>>(hg);
    scan2_k<<<dim3(Dq/256, 1, Bq), 256>>>();
    scan3_k<<<dim3(Dq/256, NCHUNK, Bq), 256>>>(x1, x2, out + (size_t)Mq*Dq);

    // 3) ff block
    rmsnorm_k<<<Mq, 256>>>(x2, ff_norm_g, xn);
    gemm_nt<2><<<dim3(4*Dq/128, Mq/128), 256>>>(xn, ff_w1, ff_b1, nullptr, h4, 4*Dq, Dq);
    gemm_nt<3><<<dim3(Dq/128, Mq/128), 256>>>(h4, ff_w2, ff_b2, x2, out, Dq, 4*Dq);
}

// round 3
// speedup vs baseline: 1.8635x; 1.8635x over previous
#include <cuda_runtime.h>
#include <math.h>
#include <stdint.h>

#define Bq 4
#define Lq 4096
#define Dq 1024
#define Mq (Bq*Lq)              // 16384 rows
#define CHUNK 128
#define NCHUNK (Lq/CHUNK)       // 32

// ---------------- scratch (static device allocations) ----------------
__device__ float g_xn[(size_t)Mq*Dq];       // rmsnorm output (reused 3x)
__device__ float g_y [(size_t)Mq*Dq];       // dwconv output
__device__ float g_x1[(size_t)Mq*Dq];       // after conv block residual
__device__ float g_x2[(size_t)Mq*Dq];       // after gru residual
__device__ float g_c [(size_t)Mq*Dq];       // scan coeffs
__device__ float g_v [(size_t)Mq*Dq];       // scan values
__device__ float g_hg[(size_t)Mq*2*Dq];     // gru pre-activations
__device__ float g_h4[(size_t)Mq*4*Dq];     // ff intermediate
__device__ float g_Hc[Bq*NCHUNK*Dq];        // per-chunk scan value
__device__ float g_Cc[Bq*NCHUNK*Dq];        // per-chunk coeff product
__device__ float g_Hi[Bq*NCHUNK*Dq];        // per-chunk initial h

// ---------------- rmsnorm ----------------
__global__ __launch_bounds__(256) void rmsnorm_k(const float* __restrict__ x,
                                                 const float* __restrict__ g,
                                                 float* __restrict__ out)
{
    const int row = blockIdx.x;
    const int tid = threadIdx.x;
    const float4* xr = (const float4*)(x + (size_t)row * Dq);
    float4 xv = xr[tid];
    float s = xv.x*xv.x + xv.y*xv.y + xv.z*xv.z + xv.w*xv.w;
    #pragma unroll
    for (int o = 16; o > 0; o >>= 1) s += __shfl_xor_sync(0xffffffffu, s, o);
    __shared__ float red[8];
    if ((tid & 31) == 0) red[tid >> 5] = s;
    __syncthreads();
    if (tid < 32) {
        float t2 = (tid < 8) ? red[tid] : 0.f;
        #pragma unroll
        for (int o = 4; o > 0; o >>= 1) t2 += __shfl_xor_sync(0xffffffffu, t2, o);
        if (tid == 0) red[0] = t2;
    }
    __syncthreads();
    float inv = 32.0f / fmaxf(sqrtf(red[0]), 1e-12f);
    const float4 gv = ((const float4*)g)[tid];
    float4 o4;
    o4.x = xv.x * inv * (gv.x + 1.f);
    o4.y = xv.y * inv * (gv.y + 1.f);
    o4.z = xv.z * inv * (gv.z + 1.f);
    o4.w = xv.w * inv * (gv.w + 1.f);
    ((float4*)(out + (size_t)row * Dq))[tid] = o4;
}

// ---------------- causal depthwise conv (K=3) + bias ----------------
__global__ __launch_bounds__(256) void dwconv_k(const float* __restrict__ wdw,
                                                const float* __restrict__ bdw)
{
    size_t idx = (size_t)blockIdx.x * 256 + threadIdx.x;
    int d = (int)(idx % Dq);
    size_t row = idx / Dq;
    int l = (int)(row % Lq);
    float w0 = wdw[d*3+0], w1 = wdw[d*3+1], w2 = wdw[d*3+2];
    float acc = bdw[d] + w2 * g_xn[idx];
    if (l >= 1) acc += w1 * g_xn[idx - Dq];
    if (l >= 2) acc += w0 * g_xn[idx - 2*Dq];
    g_y[idx] = acc;
}

// ---------------- tf32 tensor-core NT GEMM ----------------
// C[M,N] = A[M,K] * B[N,K]^T
// MODE 0/3: +bias +res ; MODE 1: plain ; MODE 2: +bias, exact gelu
__device__ __forceinline__ uint32_t f2tf(float f) {
    uint32_t u; asm("cvt.rna.tf32.f32 %0, %1;" : "=r"(u) : "f"(f)); return u;
}
__device__ __forceinline__ void mma_tf32(float* c, const uint32_t* a, const uint32_t* b) {
    asm volatile(
        "mma.sync.aligned.m16n8k8.row.col.f32.tf32.tf32.f32 "
        "{%0,%1,%2,%3}, {%4,%5,%6,%7}, {%8,%9}, {%0,%1,%2,%3};"
        : "+f"(c[0]), "+f"(c[1]), "+f"(c[2]), "+f"(c[3])
        : "r"(a[0]), "r"(a[1]), "r"(a[2]), "r"(a[3]), "r"(b[0]), "r"(b[1]));
}

#define BKp 36   // 32 + 4 pad -> conflict-free fragment LDS

template<int MODE>
__global__ __launch_bounds__(256) void gemm_tc(
    const float* __restrict__ A, const float* __restrict__ Bm,
    const float* __restrict__ bias, const float* __restrict__ res,
    float* __restrict__ C, int N_, int K_)
{
    __shared__ uint32_t As[128*BKp];
    __shared__ uint32_t Bs[128*BKp];

    const int tid  = threadIdx.x;
    const int lane = tid & 31;
    const int g    = lane >> 2;       // 0..7
    const int t    = lane & 3;        // 0..3
    const int wid  = tid >> 5;        // 0..7
    const int wm   = (wid >> 2) * 64; // warp M offset (0,64)
    const int wn   = (wid & 3) * 32;  // warp N offset (0..96)
    const int bm   = blockIdx.y * 128;
    const int bn   = blockIdx.x * 128;

    // global loader mapping: 256 thr, 4 rows-passes of 32 rows, 8 float4/row
    const int lrow = tid >> 3;        // 0..31
    const int lkc  = (tid & 7) << 2;  // 0,4,...,28

    float acc[4][4][4];
    #pragma unroll
    for (int mi = 0; mi < 4; mi++)
        #pragma unroll
        for (int ni = 0; ni < 4; ni++)
            #pragma unroll
            for (int r = 0; r < 4; r++) acc[mi][ni][r] = 0.f;

    float4 pa[4], pb[4];
    // prefetch k0 = 0
    #pragma unroll
    for (int p = 0; p < 4; p++) {
        int row = p*32 + lrow;
        pa[p] = *(const float4*)(A  + (size_t)(bm + row) * K_ + lkc);
        pb[p] = *(const float4*)(Bm + (size_t)(bn + row) * K_ + lkc);
    }

    const int niter = K_ >> 5;
    for (int it = 0; it < niter; it++) {
        // store prefetched tile (tf32-converted)
        #pragma unroll
        for (int p = 0; p < 4; p++) {
            int row = p*32 + lrow;
            uint32_t* a = &As[row*BKp + lkc];
            a[0]=f2tf(pa[p].x); a[1]=f2tf(pa[p].y); a[2]=f2tf(pa[p].z); a[3]=f2tf(pa[p].w);
            uint32_t* b = &Bs[row*BKp + lkc];
            b[0]=f2tf(pb[p].x); b[1]=f2tf(pb[p].y); b[2]=f2tf(pb[p].z); b[3]=f2tf(pb[p].w);
        }
        __syncthreads();

        // prefetch next tile
        if (it + 1 < niter) {
            int k0 = (it + 1) << 5;
            #pragma unroll
            for (int p = 0; p < 4; p++) {
                int row = p*32 + lrow;
                pa[p] = *(const float4*)(A  + (size_t)(bm + row) * K_ + k0 + lkc);
                pb[p] = *(const float4*)(Bm + (size_t)(bn + row) * K_ + k0 + lkc);
            }
        }

        // compute 4 k-steps of 8
        #pragma unroll
        for (int kk = 0; kk < 4; kk++) {
            uint32_t af[4][4];
            #pragma unroll
            for (int mi = 0; mi < 4; mi++) {
                const uint32_t* base = &As[(wm + mi*16 + g)*BKp + kk*8];
                af[mi][0] = base[t];
                af[mi][1] = base[8*BKp + t];
                af[mi][2] = base[t + 4];
                af[mi][3] = base[8*BKp + t + 4];
            }
            uint32_t bf[4][2];
            #pragma unroll
            for (int ni = 0; ni < 4; ni++) {
                const uint32_t* base = &Bs[(wn + ni*8 + g)*BKp + kk*8];
                bf[ni][0] = base[t];
                bf[ni][1] = base[t + 4];
            }
            #pragma unroll
            for (int mi = 0; mi < 4; mi++)
                #pragma unroll
                for (int ni = 0; ni < 4; ni++)
                    mma_tf32(acc[mi][ni], af[mi], bf[ni]);
        }
        __syncthreads();
    }

    // ---------------- epilogue ----------------
    #pragma unroll
    for (int mi = 0; mi < 4; mi++) {
        #pragma unroll
        for (int ni = 0; ni < 4; ni++) {
            int row0 = bm + wm + mi*16 + g;
            int col  = bn + wn + ni*8 + 2*t;
            #pragma unroll
            for (int h = 0; h < 2; h++) {
                int row = row0 + h*8;
                float v0 = acc[mi][ni][2*h + 0];
                float v1 = acc[mi][ni][2*h + 1];
                if (MODE == 0 || MODE == 3) {
                    v0 += bias[col]   + res[(size_t)row * N_ + col];
                    v1 += bias[col+1] + res[(size_t)row * N_ + col + 1];
                } else if (MODE == 2) {
                    v0 += bias[col];
                    v1 += bias[col+1];
                    v0 = 0.5f * v0 * (1.f + erff(v0 * 0.70710678118654752f));
                    v1 = 0.5f * v1 * (1.f + erff(v1 * 0.70710678118654752f));
                }
                *(float2*)(C + (size_t)row * N_ + col) = make_float2(v0, v1);
            }
        }
    }
}

// ---------------- minGRU chunked scan ----------------
__global__ __launch_bounds__(256) void scan1_k(const float* __restrict__ hg)
{
    int d  = blockIdx.x * 256 + threadIdx.x;
    int ch = blockIdx.y;
    int b  = blockIdx.z;
    size_t row0 = (size_t)b * Lq + (size_t)ch * CHUNK;
    float h = 0.f, cp = 1.f;
    for (int t = 0; t < CHUNK; t++) {
        size_t r = row0 + t;
        float hd = hg[r*2*Dq + d];
        float gg = hg[r*2*Dq + Dq + d];
        float sp = fmaxf(gg, 0.f) + log1pf(expf(-fabsf(gg)));
        float lg = (hd >= 0.f) ? logf(hd + 0.5f) : (hd - log1pf(expf(hd)));
        float c = expf(-sp);
        float v = expf(gg - sp + lg);
        g_c[r*Dq + d] = c;
        g_v[r*Dq + d] = v;
        h = fmaf(c, h, v);
        cp *= c;
    }
    int sidx = (b*NCHUNK + ch)*Dq + d;
    g_Hc[sidx] = h;
    g_Cc[sidx] = cp;
}

__global__ __launch_bounds__(256) void scan2_k()
{
    int d = blockIdx.x * 256 + threadIdx.x;
    int b = blockIdx.z;
    float h = 0.f;
    for (int ch = 0; ch < NCHUNK; ch++) {
        int sidx = (b*NCHUNK + ch)*Dq + d;
        g_Hi[sidx] = h;
        h = fmaf(g_Cc[sidx], h, g_Hc[sidx]);
    }
}

__global__ __launch_bounds__(256) void scan3_k(const float* __restrict__ x1,
                                               float* __restrict__ x2,
                                               float* __restrict__ nh)
{
    int d  = blockIdx.x * 256 + threadIdx.x;
    int ch = blockIdx.y;
    int b  = blockIdx.z;
    size_t row0 = (size_t)b * Lq + (size_t)ch * CHUNK;
    float h = g_Hi[(b*NCHUNK + ch)*Dq + d];
    for (int t = 0; t < CHUNK; t++) {
        size_t r = row0 + t;
        h = fmaf(g_c[r*Dq + d], h, g_v[r*Dq + d]);
        x2[r*Dq + d] = h + x1[r*Dq + d];
    }
    if (ch == NCHUNK - 1) nh[b*Dq + d] = h;
}

// ---------------- launch ----------------
extern "C" void kernel_launch(void* const* d_in, const int* in_sizes, int n_in,
                              void* d_out, int out_size)
{
    const float* x           = (const float*)d_in[0];
    const float* conv_dw_w   = (const float*)d_in[1];
    const float* conv_dw_b   = (const float*)d_in[2];
    const float* conv_pw_w   = (const float*)d_in[3];
    const float* conv_pw_b   = (const float*)d_in[4];
    const float* conv_norm_g = (const float*)d_in[5];
    const float* gru_norm_g  = (const float*)d_in[6];
    const float* gru_w       = (const float*)d_in[7];
    const float* ff_norm_g   = (const float*)d_in[8];
    const float* ff_w1       = (const float*)d_in[9];
    const float* ff_b1       = (const float*)d_in[10];
    const float* ff_w2       = (const float*)d_in[11];
    const float* ff_b2       = (const float*)d_in[12];
    float* out = (float*)d_out;

    float *xn, *y, *x1, *x2, *hg, *h4;
    cudaGetSymbolAddress((void**)&xn, g_xn);
    cudaGetSymbolAddress((void**)&y,  g_y);
    cudaGetSymbolAddress((void**)&x1, g_x1);
    cudaGetSymbolAddress((void**)&x2, g_x2);
    cudaGetSymbolAddress((void**)&hg, g_hg);
    cudaGetSymbolAddress((void**)&h4, g_h4);

    // 1) conv block
    rmsnorm_k<<<Mq, 256>>>(x, conv_norm_g, xn);
    dwconv_k<<<(Mq*(size_t)Dq)/256, 256>>>(conv_dw_w, conv_dw_b);
    gemm_tc<0><<<dim3(Dq/128, Mq/128), 256>>>(y, conv_pw_w, conv_pw_b, x, x1, Dq, Dq);

    // 2) gru block
    rmsnorm_k<<<Mq, 256>>>(x1, gru_norm_g, xn);
    gemm_tc<1><<<dim3(2*Dq/128, Mq/128), 256>>>(xn, gru_w, nullptr, nullptr, hg, 2*Dq, Dq);
    scan1_k<<<dim3(Dq/256, NCHUNK, Bq), 256>>>(hg);
    scan2_k<<<dim3(Dq/256, 1, Bq), 256>>>();
    scan3_k<<<dim3(Dq/256, NCHUNK, Bq), 256>>>(x1, x2, out + (size_t)Mq*Dq);

    // 3) ff block
    rmsnorm_k<<<Mq, 256>>>(x2, ff_norm_g, xn);
    gemm_tc<2><<<dim3(4*Dq/128, Mq/128), 256>>>(xn, ff_w1, ff_b1, nullptr, h4, 4*Dq, Dq);
    gemm_tc<3><<<dim3(Dq/128, Mq/128), 256>>>(h4, ff_w2, ff_b2, x2, out, Dq, 4*Dq);
}

// round 8
// speedup vs baseline: 2.0295x; 1.0890x over previous
#include <cuda_runtime.h>
#include <math.h>
#include <stdint.h>

#define Bq 4
#define Lq 4096
#define Dq 1024
#define Mq (Bq*Lq)              // 16384 rows
#define CHUNK 128
#define NCHUNK (Lq/CHUNK)       // 32

// ---------------- scratch (static device allocations) ----------------
__device__ float g_xn[(size_t)Mq*Dq];       // rmsnorm output (reused 3x)
__device__ float g_y [(size_t)Mq*Dq];       // dwconv output
__device__ float g_x1[(size_t)Mq*Dq];       // after conv block residual
__device__ float g_x2[(size_t)Mq*Dq];       // after gru residual
__device__ float g_c [(size_t)Mq*Dq];       // scan coeffs
__device__ float g_v [(size_t)Mq*Dq];       // scan values
__device__ float g_hg[(size_t)Mq*2*Dq];     // gru pre-activations
__device__ float g_h4[(size_t)Mq*4*Dq];     // ff intermediate
__device__ float g_Hc[Bq*NCHUNK*Dq];        // per-chunk scan value
__device__ float g_Cc[Bq*NCHUNK*Dq];        // per-chunk coeff product
__device__ float g_Hi[Bq*NCHUNK*Dq];        // per-chunk initial h

// ---------------- rmsnorm ----------------
__global__ __launch_bounds__(256) void rmsnorm_k(const float* __restrict__ x,
                                                 const float* __restrict__ g,
                                                 float* __restrict__ out)
{
    const int row = blockIdx.x;
    const int tid = threadIdx.x;
    const float4* xr = (const float4*)(x + (size_t)row * Dq);
    float4 xv = xr[tid];
    float s = xv.x*xv.x + xv.y*xv.y + xv.z*xv.z + xv.w*xv.w;
    #pragma unroll
    for (int o = 16; o > 0; o >>= 1) s += __shfl_xor_sync(0xffffffffu, s, o);
    __shared__ float red[8];
    if ((tid & 31) == 0) red[tid >> 5] = s;
    __syncthreads();
    if (tid < 32) {
        float t2 = (tid < 8) ? red[tid] : 0.f;
        #pragma unroll
        for (int o = 4; o > 0; o >>= 1) t2 += __shfl_xor_sync(0xffffffffu, t2, o);
        if (tid == 0) red[0] = t2;
    }
    __syncthreads();
    float inv = 32.0f / fmaxf(sqrtf(red[0]), 1e-12f);
    const float4 gv = ((const float4*)g)[tid];
    float4 o4;
    o4.x = xv.x * inv * (gv.x + 1.f);
    o4.y = xv.y * inv * (gv.y + 1.f);
    o4.z = xv.z * inv * (gv.z + 1.f);
    o4.w = xv.w * inv * (gv.w + 1.f);
    ((float4*)(out + (size_t)row * Dq))[tid] = o4;
}

// ---------------- causal depthwise conv (K=3) + bias ----------------
__global__ __launch_bounds__(256) void dwconv_k(const float* __restrict__ wdw,
                                                const float* __restrict__ bdw)
{
    size_t idx = (size_t)blockIdx.x * 256 + threadIdx.x;
    int d = (int)(idx % Dq);
    size_t row = idx / Dq;
    int l = (int)(row % Lq);
    float w0 = wdw[d*3+0], w1 = wdw[d*3+1], w2 = wdw[d*3+2];
    float acc = bdw[d] + w2 * g_xn[idx];
    if (l >= 1) acc += w1 * g_xn[idx - Dq];
    if (l >= 2) acc += w0 * g_xn[idx - 2*Dq];
    g_y[idx] = acc;
}

// ---------------- tf32 tensor-core NT GEMM ----------------
// C[M,N] = A[M,K] * B[N,K]^T
// MODE 0/3: +bias +res ; MODE 1: plain ; MODE 2: +bias, exact gelu
//
// Shared tiles stored in MMA-FRAGMENT ORDER so each warp fetches its
// m16n8k8 A-fragment with one LDS.128 and B-fragment with one LDS.64.
//   A: idx = mrow*512 + kk*128 + g*16 + (t^kk)*4 + reg   (reg = khalf*2 + rhalf)
//   B: idx = ngrp*256 + kk*64  + g*8  + (t^kk)*2 + reg   (reg = khalf)
// The t^kk swizzle keeps stores conflict-light and loads conflict-free.
__device__ __forceinline__ uint32_t f2tf(float f) {
    uint32_t u; asm("cvt.rna.tf32.f32 %0, %1;" : "=r"(u) : "f"(f)); return u;
}
__device__ __forceinline__ void mma_tf32(float* c, const uint32_t* a, const uint32_t* b) {
    asm volatile(
        "mma.sync.aligned.m16n8k8.row.col.f32.tf32.tf32.f32 "
        "{%0,%1,%2,%3}, {%4,%5,%6,%7}, {%8,%9}, {%0,%1,%2,%3};"
        : "+f"(c[0]), "+f"(c[1]), "+f"(c[2]), "+f"(c[3])
        : "r"(a[0]), "r"(a[1]), "r"(a[2]), "r"(a[3]), "r"(b[0]), "r"(b[1]));
}

template<int MODE>
__global__ __launch_bounds__(256) void gemm_tc(
    const float* __restrict__ A, const float* __restrict__ Bm,
    const float* __restrict__ bias, const float* __restrict__ res,
    float* __restrict__ C, int N_, int K_)
{
    __shared__ __align__(16) uint32_t As[4096];   // 128 x 32 in frag order
    __shared__ __align__(16) uint32_t Bs[4096];   // 128 x 32 in frag order

    const int tid  = threadIdx.x;
    const int lane = tid & 31;
    const int g    = lane >> 2;       // 0..7
    const int t    = lane & 3;        // 0..3
    const int wid  = tid >> 5;        // 0..7
    const int wm4  = (wid >> 2) * 4;  // warp M tile group (mrow base)
    const int wn4  = (wid & 3) * 4;   // warp N tile group (ngrp base)
    const int bm   = blockIdx.y * 128;
    const int bn   = blockIdx.x * 128;

    // global loader mapping: 256 thr, 4 passes of 32 rows, 8 float4/row
    const int lrow = tid >> 3;        // 0..31
    const int lkc  = (tid & 7) << 2;  // 0,4,...,28
    const int kk_s    = lkc >> 3;          // store-side kk
    const int khalf_s = (lkc >> 2) & 1;    // store-side k half

    float acc[4][4][4];
    #pragma unroll
    for (int mi = 0; mi < 4; mi++)
        #pragma unroll
        for (int ni = 0; ni < 4; ni++)
            #pragma unroll
            for (int r = 0; r < 4; r++) acc[mi][ni][r] = 0.f;

    float4 pa[4], pb[4];
    #pragma unroll
    for (int p = 0; p < 4; p++) {
        int row = p*32 + lrow;
        pa[p] = *(const float4*)(A  + (size_t)(bm + row) * K_ + lkc);
        pb[p] = *(const float4*)(Bm + (size_t)(bn + row) * K_ + lkc);
    }

    const int niter = K_ >> 5;
    for (int it = 0; it < niter; it++) {
        // store prefetched tile into fragment-order smem (tf32-converted)
        #pragma unroll
        for (int p = 0; p < 4; p++) {
            int row  = p*32 + lrow;
            // A placement
            int mrow = row >> 4;
            int ri   = row & 15;
            int rhalfA = ri >> 3;
            int gA   = ri & 7;
            int abase = mrow*512 + kk_s*128 + gA*16;
            int areg  = khalf_s*2 + rhalfA;
            // B placement
            int ngrp = row >> 3;
            int gB   = row & 7;
            int bbase = ngrp*256 + kk_s*64 + gB*8;
            float av[4] = {pa[p].x, pa[p].y, pa[p].z, pa[p].w};
            float bv[4] = {pb[p].x, pb[p].y, pb[p].z, pb[p].w};
            #pragma unroll
            for (int j = 0; j < 4; j++) {
                int tp = j ^ kk_s;
                As[abase + tp*4 + areg]    = f2tf(av[j]);
                Bs[bbase + tp*2 + khalf_s] = f2tf(bv[j]);
            }
        }
        __syncthreads();

        // prefetch next tile
        if (it + 1 < niter) {
            int k0 = (it + 1) << 5;
            #pragma unroll
            for (int p = 0; p < 4; p++) {
                int row = p*32 + lrow;
                pa[p] = *(const float4*)(A  + (size_t)(bm + row) * K_ + k0 + lkc);
                pb[p] = *(const float4*)(Bm + (size_t)(bn + row) * K_ + k0 + lkc);
            }
        }

        // compute 4 k-steps of 8
        #pragma unroll
        for (int kk = 0; kk < 4; kk++) {
            const int tp = t ^ kk;
            uint4 af[4];
            #pragma unroll
            for (int mi = 0; mi < 4; mi++)
                af[mi] = *(const uint4*)&As[(wm4 + mi)*512 + kk*128 + g*16 + tp*4];
            uint2 bf[4];
            #pragma unroll
            for (int ni = 0; ni < 4; ni++)
                bf[ni] = *(const uint2*)&Bs[(wn4 + ni)*256 + kk*64 + g*8 + tp*2];
            #pragma unroll
            for (int mi = 0; mi < 4; mi++)
                #pragma unroll
                for (int ni = 0; ni < 4; ni++)
                    mma_tf32(acc[mi][ni], (const uint32_t*)&af[mi], (const uint32_t*)&bf[ni]);
        }
        __syncthreads();
    }

    // ---------------- epilogue ----------------
    #pragma unroll
    for (int mi = 0; mi < 4; mi++) {
        #pragma unroll
        for (int ni = 0; ni < 4; ni++) {
            int row0 = bm + (wm4 + mi)*16 + g;
            int col  = bn + (wn4 + ni)*8 + 2*t;
            #pragma unroll
            for (int h = 0; h < 2; h++) {
                int row = row0 + h*8;
                float v0 = acc[mi][ni][2*h + 0];
                float v1 = acc[mi][ni][2*h + 1];
                if (MODE == 0 || MODE == 3) {
                    v0 += bias[col]   + res[(size_t)row * N_ + col];
                    v1 += bias[col+1] + res[(size_t)row * N_ + col + 1];
                } else if (MODE == 2) {
                    v0 += bias[col];
                    v1 += bias[col+1];
                    v0 = 0.5f * v0 * (1.f + erff(v0 * 0.70710678118654752f));
                    v1 = 0.5f * v1 * (1.f + erff(v1 * 0.70710678118654752f));
                }
                *(float2*)(C + (size_t)row * N_ + col) = make_float2(v0, v1);
            }
        }
    }
}

// ---------------- minGRU chunked scan ----------------
__global__ __launch_bounds__(256) void scan1_k(const float* __restrict__ hg)
{
    int d  = blockIdx.x * 256 + threadIdx.x;
    int ch = blockIdx.y;
    int b  = blockIdx.z;
    size_t row0 = (size_t)b * Lq + (size_t)ch * CHUNK;
    float h = 0.f, cp = 1.f;
    for (int t = 0; t < CHUNK; t++) {
        size_t r = row0 + t;
        float hd = hg[r*2*Dq + d];
        float gg = hg[r*2*Dq + Dq + d];
        float sp = fmaxf(gg, 0.f) + log1pf(expf(-fabsf(gg)));
        float lg = (hd >= 0.f) ? logf(hd + 0.5f) : (hd - log1pf(expf(hd)));
        float c = expf(-sp);
        float v = expf(gg - sp + lg);
        g_c[r*Dq + d] = c;
        g_v[r*Dq + d] = v;
        h = fmaf(c, h, v);
        cp *= c;
    }
    int sidx = (b*NCHUNK + ch)*Dq + d;
    g_Hc[sidx] = h;
    g_Cc[sidx] = cp;
}

__global__ __launch_bounds__(256) void scan2_k()
{
    int d = blockIdx.x * 256 + threadIdx.x;
    int b = blockIdx.z;
    float h = 0.f;
    for (int ch = 0; ch < NCHUNK; ch++) {
        int sidx = (b*NCHUNK + ch)*Dq + d;
        g_Hi[sidx] = h;
        h = fmaf(g_Cc[sidx], h, g_Hc[sidx]);
    }
}

__global__ __launch_bounds__(256) void scan3_k(const float* __restrict__ x1,
                                               float* __restrict__ x2,
                                               float* __restrict__ nh)
{
    int d  = blockIdx.x * 256 + threadIdx.x;
    int ch = blockIdx.y;
    int b  = blockIdx.z;
    size_t row0 = (size_t)b * Lq + (size_t)ch * CHUNK;
    float h = g_Hi[(b*NCHUNK + ch)*Dq + d];
    for (int t = 0; t < CHUNK; t++) {
        size_t r = row0 + t;
        h = fmaf(g_c[r*Dq + d], h, g_v[r*Dq + d]);
        x2[r*Dq + d] = h + x1[r*Dq + d];
    }
    if (ch == NCHUNK - 1) nh[b*Dq + d] = h;
}

// ---------------- launch ----------------
extern "C" void kernel_launch(void* const* d_in, const int* in_sizes, int n_in,
                              void* d_out, int out_size)
{
    const float* x           = (const float*)d_in[0];
    const float* conv_dw_w   = (const float*)d_in[1];
    const float* conv_dw_b   = (const float*)d_in[2];
    const float* conv_pw_w   = (const float*)d_in[3];
    const float* conv_pw_b   = (const float*)d_in[4];
    const float* conv_norm_g = (const float*)d_in[5];
    const float* gru_norm_g  = (const float*)d_in[6];
    const float* gru_w       = (const float*)d_in[7];
    const float* ff_norm_g   = (const float*)d_in[8];
    const float* ff_w1       = (const float*)d_in[9];
    const float* ff_b1       = (const float*)d_in[10];
    const float* ff_w2       = (const float*)d_in[11];
    const float* ff_b2       = (const float*)d_in[12];
    float* out = (float*)d_out;

    float *xn, *y, *x1, *x2, *hg, *h4;
    cudaGetSymbolAddress((void**)&xn, g_xn);
    cudaGetSymbolAddress((void**)&y,  g_y);
    cudaGetSymbolAddress((void**)&x1, g_x1);
    cudaGetSymbolAddress((void**)&x2, g_x2);
    cudaGetSymbolAddress((void**)&hg, g_hg);
    cudaGetSymbolAddress((void**)&h4, g_h4);

    // 1) conv block
    rmsnorm_k<<<Mq, 256>>>(x, conv_norm_g, xn);
    dwconv_k<<<(Mq*(size_t)Dq)/256, 256>>>(conv_dw_w, conv_dw_b);
    gemm_tc<0><<<dim3(Dq/128, Mq/128), 256>>>(y, conv_pw_w, conv_pw_b, x, x1, Dq, Dq);

    // 2) gru block
    rmsnorm_k<<<Mq, 256>>>(x1, gru_norm_g, xn);
    gemm_tc<1><<<dim3(2*Dq/128, Mq/128), 256>>>(xn, gru_w, nullptr, nullptr, hg, 2*Dq, Dq);
    scan1_k<<<dim3(Dq/256, NCHUNK, Bq), 256>>>(hg);
    scan2_k<<<dim3(Dq/256, 1, Bq), 256>>>();
    scan3_k<<<dim3(Dq/256, NCHUNK, Bq), 256>>>(x1, x2, out + (size_t)Mq*Dq);

    // 3) ff block
    rmsnorm_k<<<Mq, 256>>>(x2, ff_norm_g, xn);
    gemm_tc<2><<<dim3(4*Dq/128, Mq/128), 256>>>(xn, ff_w1, ff_b1, nullptr, h4, 4*Dq, Dq);
    gemm_tc<3><<<dim3(Dq/128, Mq/128), 256>>>(h4, ff_w2, ff_b2, x2, out, Dq, 4*Dq);
}

// round 11
// speedup vs baseline: 3.7066x; 1.8264x over previous
#include <cuda_runtime.h>
#include <math.h>
#include <stdint.h>

#define Bq 4
#define Lq 4096
#define Dq 1024
#define Mq (Bq*Lq)              // 16384 rows
#define CHUNK 128
#define NCHUNK (Lq/CHUNK)       // 32

// ---------------- scratch (static device allocations) ----------------
__device__ float g_xn[(size_t)Mq*Dq];
__device__ float g_y [(size_t)Mq*Dq];
__device__ float g_x1[(size_t)Mq*Dq];
__device__ float g_x2[(size_t)Mq*Dq];
__device__ float g_c [(size_t)Mq*Dq];
__device__ float g_v [(size_t)Mq*Dq];
__device__ float g_hg[(size_t)Mq*2*Dq];
__device__ float g_h4[(size_t)Mq*4*Dq];
__device__ float g_Hc[Bq*NCHUNK*Dq];
__device__ float g_Cc[Bq*NCHUNK*Dq];
__device__ float g_Hi[Bq*NCHUNK*Dq];

// ---------------- rmsnorm ----------------
__global__ __launch_bounds__(256) void rmsnorm_k(const float* __restrict__ x,
                                                 const float* __restrict__ g,
                                                 float* __restrict__ out)
{
    const int row = blockIdx.x;
    const int tid = threadIdx.x;
    const float4* xr = (const float4*)(x + (size_t)row * Dq);
    float4 xv = xr[tid];
    float s = xv.x*xv.x + xv.y*xv.y + xv.z*xv.z + xv.w*xv.w;
    #pragma unroll
    for (int o = 16; o > 0; o >>= 1) s += __shfl_xor_sync(0xffffffffu, s, o);
    __shared__ float red[8];
    if ((tid & 31) == 0) red[tid >> 5] = s;
    __syncthreads();
    if (tid < 32) {
        float t2 = (tid < 8) ? red[tid] : 0.f;
        #pragma unroll
        for (int o = 4; o > 0; o >>= 1) t2 += __shfl_xor_sync(0xffffffffu, t2, o);
        if (tid == 0) red[0] = t2;
    }
    __syncthreads();
    float inv = 32.0f / fmaxf(sqrtf(red[0]), 1e-12f);
    const float4 gv = ((const float4*)g)[tid];
    float4 o4;
    o4.x = xv.x * inv * (gv.x + 1.f);
    o4.y = xv.y * inv * (gv.y + 1.f);
    o4.z = xv.z * inv * (gv.z + 1.f);
    o4.w = xv.w * inv * (gv.w + 1.f);
    ((float4*)(out + (size_t)row * Dq))[tid] = o4;
}

// ---------------- causal depthwise conv (K=3) + bias ----------------
__global__ __launch_bounds__(256) void dwconv_k(const float* __restrict__ wdw,
                                                const float* __restrict__ bdw)
{
    size_t idx = (size_t)blockIdx.x * 256 + threadIdx.x;
    int d = (int)(idx % Dq);
    size_t row = idx / Dq;
    int l = (int)(row % Lq);
    float w0 = wdw[d*3+0], w1 = wdw[d*3+1], w2 = wdw[d*3+2];
    float acc = bdw[d] + w2 * g_xn[idx];
    if (l >= 1) acc += w1 * g_xn[idx - Dq];
    if (l >= 2) acc += w0 * g_xn[idx - 2*Dq];
    g_y[idx] = acc;
}

// ---------------- fp16 tensor-core NT GEMM (fp32 accum) ----------------
// C[M,N] = A[M,K] * B[N,K]^T ; m16n8k16 fragments stored in frag order.
//   A: idx = ((mrow*2+kk)*8 + g)*16 + (t^kk)*4 + reg  (reg = hi + khi*2)
//   B: idx = ((ngrp*2+kk)*8 + g)*8  + (t^kk)*2 + khi
// MODE 0/3: +bias +res ; MODE 1: plain ; MODE 2: +bias exact gelu
__device__ __forceinline__ uint32_t f32x2_h2(float lo, float hi) {
    uint32_t r;
    asm("cvt.rn.f16x2.f32 %0, %1, %2;" : "=r"(r) : "f"(hi), "f"(lo));
    return r;
}
__device__ __forceinline__ void mma_f16(float* c, const uint32_t* a, const uint32_t* b) {
    asm volatile(
        "mma.sync.aligned.m16n8k16.row.col.f32.f16.f16.f32 "
        "{%0,%1,%2,%3}, {%4,%5,%6,%7}, {%8,%9}, {%0,%1,%2,%3};"
        : "+f"(c[0]), "+f"(c[1]), "+f"(c[2]), "+f"(c[3])
        : "r"(a[0]), "r"(a[1]), "r"(a[2]), "r"(a[3]), "r"(b[0]), "r"(b[1]));
}

template<int MODE>
__global__ __launch_bounds__(256) void gemm_tc(
    const float* __restrict__ A, const float* __restrict__ Bm,
    const float* __restrict__ bias, const float* __restrict__ res,
    float* __restrict__ C, int N_, int K_)
{
    __shared__ __align__(16) uint32_t As[2048];   // 128 x 32 f16 in frag order
    __shared__ __align__(16) uint32_t Bs[2048];   // 128 x 32 f16 in frag order

    const int tid  = threadIdx.x;
    const int lane = tid & 31;
    const int g    = lane >> 2;       // 0..7
    const int t    = lane & 3;        // 0..3
    const int wid  = tid >> 5;        // 0..7
    const int wm4  = (wid >> 2) * 4;  // warp mrow base (0 or 4)
    const int wn4  = (wid & 3) * 4;   // warp ngrp base (0,4,8,12)
    const int bm   = blockIdx.y * 128;
    const int bn   = blockIdx.x * 128;

    // loader mapping: 256 thr, 4 passes of 32 rows, 8 float4/row (BK=32)
    const int lrow = tid >> 3;        // 0..31
    const int lkc  = (tid & 7) << 2;  // 0,4,...,28
    const int kk_s  = lkc >> 4;           // k16 step of this store
    const int kin   = lkc & 15;
    const int khi_s = kin >> 3;
    const int tb_s  = (kin & 7) >> 1;     // 0 or 2

    float acc[4][4][4];
    #pragma unroll
    for (int mi = 0; mi < 4; mi++)
        #pragma unroll
        for (int ni = 0; ni < 4; ni++)
            #pragma unroll
            for (int r = 0; r < 4; r++) acc[mi][ni][r] = 0.f;

    float4 pa[4], pb[4];
    #pragma unroll
    for (int p = 0; p < 4; p++) {
        int row = p*32 + lrow;
        pa[p] = *(const float4*)(A  + (size_t)(bm + row) * K_ + lkc);
        pb[p] = *(const float4*)(Bm + (size_t)(bn + row) * K_ + lkc);
    }

    const int niter = K_ >> 5;
    for (int it = 0; it < niter; it++) {
        // store prefetched tile into fragment-order smem (f16-converted)
        #pragma unroll
        for (int p = 0; p < 4; p++) {
            int row  = p*32 + lrow;
            // A placement
            int mrow = row >> 4;
            int ri   = row & 15;
            int gA   = ri & 7;
            int hiA  = ri >> 3;
            int abase = ((mrow*2 + kk_s)*8 + gA)*16 + (hiA + khi_s*2);
            As[abase + ((tb_s  ) ^ kk_s)*4] = f32x2_h2(pa[p].x, pa[p].y);
            As[abase + ((tb_s+1) ^ kk_s)*4] = f32x2_h2(pa[p].z, pa[p].w);
            // B placement
            int ngrp = row >> 3;
            int gB   = row & 7;
            int bbase = ((ngrp*2 + kk_s)*8 + gB)*8 + khi_s;
            Bs[bbase + ((tb_s  ) ^ kk_s)*2] = f32x2_h2(pb[p].x, pb[p].y);
            Bs[bbase + ((tb_s+1) ^ kk_s)*2] = f32x2_h2(pb[p].z, pb[p].w);
        }
        __syncthreads();

        // prefetch next tile
        if (it + 1 < niter) {
            int k0 = (it + 1) << 5;
            #pragma unroll
            for (int p = 0; p < 4; p++) {
                int row = p*32 + lrow;
                pa[p] = *(const float4*)(A  + (size_t)(bm + row) * K_ + k0 + lkc);
                pb[p] = *(const float4*)(Bm + (size_t)(bn + row) * K_ + k0 + lkc);
            }
        }

        // compute: 2 k16 steps
        #pragma unroll
        for (int kk = 0; kk < 2; kk++) {
            const int tp = t ^ kk;
            uint4 af[4];
            #pragma unroll
            for (int mi = 0; mi < 4; mi++)
                af[mi] = *(const uint4*)&As[(((wm4 + mi)*2 + kk)*8 + g)*16 + tp*4];
            uint2 bf[4];
            #pragma unroll
            for (int ni = 0; ni < 4; ni++)
                bf[ni] = *(const uint2*)&Bs[(((wn4 + ni)*2 + kk)*8 + g)*8 + tp*2];
            #pragma unroll
            for (int mi = 0; mi < 4; mi++)
                #pragma unroll
                for (int ni = 0; ni < 4; ni++)
                    mma_f16(acc[mi][ni], (const uint32_t*)&af[mi], (const uint32_t*)&bf[ni]);
        }
        __syncthreads();
    }

    // ---------------- epilogue ----------------
    #pragma unroll
    for (int mi = 0; mi < 4; mi++) {
        #pragma unroll
        for (int ni = 0; ni < 4; ni++) {
            int row0 = bm + (wm4 + mi)*16 + g;
            int col  = bn + (wn4 + ni)*8 + 2*t;
            #pragma unroll
            for (int h = 0; h < 2; h++) {
                int row = row0 + h*8;
                float v0 = acc[mi][ni][2*h + 0];
                float v1 = acc[mi][ni][2*h + 1];
                if (MODE == 0 || MODE == 3) {
                    v0 += bias[col]   + res[(size_t)row * N_ + col];
                    v1 += bias[col+1] + res[(size_t)row * N_ + col + 1];
                } else if (MODE == 2) {
                    v0 += bias[col];
                    v1 += bias[col+1];
                    v0 = 0.5f * v0 * (1.f + erff(v0 * 0.70710678118654752f));
                    v1 = 0.5f * v1 * (1.f + erff(v1 * 0.70710678118654752f));
                }
                *(float2*)(C + (size_t)row * N_ + col) = make_float2(v0, v1);
            }
        }
    }
}

// ---------------- minGRU chunked scan ----------------
__global__ __launch_bounds__(256) void scan1_k(const float* __restrict__ hg)
{
    int d  = blockIdx.x * 256 + threadIdx.x;
    int ch = blockIdx.y;
    int b  = blockIdx.z;
    size_t row0 = (size_t)b * Lq + (size_t)ch * CHUNK;
    float h = 0.f, cp = 1.f;
    for (int t = 0; t < CHUNK; t++) {
        size_t r = row0 + t;
        float hd = hg[r*2*Dq + d];
        float gg = hg[r*2*Dq + Dq + d];
        float sp = fmaxf(gg, 0.f) + log1pf(expf(-fabsf(gg)));
        float lg = (hd >= 0.f) ? logf(hd + 0.5f) : (hd - log1pf(expf(hd)));
        float c = expf(-sp);
        float v = expf(gg - sp + lg);
        g_c[r*Dq + d] = c;
        g_v[r*Dq + d] = v;
        h = fmaf(c, h, v);
        cp *= c;
    }
    int sidx = (b*NCHUNK + ch)*Dq + d;
    g_Hc[sidx] = h;
    g_Cc[sidx] = cp;
}

__global__ __launch_bounds__(256) void scan2_k()
{
    int d = blockIdx.x * 256 + threadIdx.x;
    int b = blockIdx.z;
    float h = 0.f;
    for (int ch = 0; ch < NCHUNK; ch++) {
        int sidx = (b*NCHUNK + ch)*Dq + d;
        g_Hi[sidx] = h;
        h = fmaf(g_Cc[sidx], h, g_Hc[sidx]);
    }
}

__global__ __launch_bounds__(256) void scan3_k(const float* __restrict__ x1,
                                               float* __restrict__ x2,
                                               float* __restrict__ nh)
{
    int d  = blockIdx.x * 256 + threadIdx.x;
    int ch = blockIdx.y;
    int b  = blockIdx.z;
    size_t row0 = (size_t)b * Lq + (size_t)ch * CHUNK;
    float h = g_Hi[(b*NCHUNK + ch)*Dq + d];
    for (int t = 0; t < CHUNK; t++) {
        size_t r = row0 + t;
        h = fmaf(g_c[r*Dq + d], h, g_v[r*Dq + d]);
        x2[r*Dq + d] = h + x1[r*Dq + d];
    }
    if (ch == NCHUNK - 1) nh[b*Dq + d] = h;
}

// ---------------- launch ----------------
extern "C" void kernel_launch(void* const* d_in, const int* in_sizes, int n_in,
                              void* d_out, int out_size)
{
    const float* x           = (const float*)d_in[0];
    const float* conv_dw_w   = (const float*)d_in[1];
    const float* conv_dw_b   = (const float*)d_in[2];
    const float* conv_pw_w   = (const float*)d_in[3];
    const float* conv_pw_b   = (const float*)d_in[4];
    const float* conv_norm_g = (const float*)d_in[5];
    const float* gru_norm_g  = (const float*)d_in[6];
    const float* gru_w       = (const float*)d_in[7];
    const float* ff_norm_g   = (const float*)d_in[8];
    const float* ff_w1       = (const float*)d_in[9];
    const float* ff_b1       = (const float*)d_in[10];
    const float* ff_w2       = (const float*)d_in[11];
    const float* ff_b2       = (const float*)d_in[12];
    float* out = (float*)d_out;

    float *xn, *y, *x1, *x2, *hg, *h4;
    cudaGetSymbolAddress((void**)&xn, g_xn);
    cudaGetSymbolAddress((void**)&y,  g_y);
    cudaGetSymbolAddress((void**)&x1, g_x1);
    cudaGetSymbolAddress((void**)&x2, g_x2);
    cudaGetSymbolAddress((void**)&hg, g_hg);
    cudaGetSymbolAddress((void**)&h4, g_h4);

    // 1) conv block
    rmsnorm_k<<<Mq, 256>>>(x, conv_norm_g, xn);
    dwconv_k<<<(Mq*(size_t)Dq)/256, 256>>>(conv_dw_w, conv_dw_b);
    gemm_tc<0><<<dim3(Dq/128, Mq/128), 256>>>(y, conv_pw_w, conv_pw_b, x, x1, Dq, Dq);

    // 2) gru block
    rmsnorm_k<<<Mq, 256>>>(x1, gru_norm_g, xn);
    gemm_tc<1><<<dim3(2*Dq/128, Mq/128), 256>>>(xn, gru_w, nullptr, nullptr, hg, 2*Dq, Dq);
    scan1_k<<<dim3(Dq/256, NCHUNK, Bq), 256>>>(hg);
    scan2_k<<<dim3(Dq/256, 1, Bq), 256>>>();
    scan3_k<<<dim3(Dq/256, NCHUNK, Bq), 256>>>(x1, x2, out + (size_t)Mq*Dq);

    // 3) ff block
    rmsnorm_k<<<Mq, 256>>>(x2, ff_norm_g, xn);
    gemm_tc<2><<<dim3(4*Dq/128, Mq/128), 256>>>(xn, ff_w1, ff_b1, nullptr, h4, 4*Dq, Dq);
    gemm_tc<3><<<dim3(Dq/128, Mq/128), 256>>>(h4, ff_w2, ff_b2, x2, out, Dq, 4*Dq);
}

// round 12
// speedup vs baseline: 4.0663x; 1.0971x over previous
#include <cuda_runtime.h>
#include <math.h>
#include <stdint.h>

#define Bq 4
#define Lq 4096
#define Dq 1024
#define Mq (Bq*Lq)              // 16384 rows
#define CHUNK 128
#define NCHUNK (Lq/CHUNK)       // 32

// ---------------- scratch (static device allocations) ----------------
__device__ float g_xn[(size_t)Mq*Dq];
__device__ float g_y [(size_t)Mq*Dq];
__device__ float g_x1[(size_t)Mq*Dq];
__device__ float g_x2[(size_t)Mq*Dq];
__device__ float g_c [(size_t)Mq*Dq];
__device__ float g_v [(size_t)Mq*Dq];
__device__ float g_hg[(size_t)Mq*2*Dq];
__device__ float g_h4[(size_t)Mq*4*Dq];
__device__ float g_Hc[Bq*NCHUNK*Dq];
__device__ float g_Cc[Bq*NCHUNK*Dq];
__device__ float g_Hi[Bq*NCHUNK*Dq];

// ---------------- rmsnorm ----------------
__global__ __launch_bounds__(256) void rmsnorm_k(const float* __restrict__ x,
                                                 const float* __restrict__ g,
                                                 float* __restrict__ out)
{
    const int row = blockIdx.x;
    const int tid = threadIdx.x;
    const float4* xr = (const float4*)(x + (size_t)row * Dq);
    float4 xv = xr[tid];
    float s = xv.x*xv.x + xv.y*xv.y + xv.z*xv.z + xv.w*xv.w;
    #pragma unroll
    for (int o = 16; o > 0; o >>= 1) s += __shfl_xor_sync(0xffffffffu, s, o);
    __shared__ float red[8];
    if ((tid & 31) == 0) red[tid >> 5] = s;
    __syncthreads();
    if (tid < 32) {
        float t2 = (tid < 8) ? red[tid] : 0.f;
        #pragma unroll
        for (int o = 4; o > 0; o >>= 1) t2 += __shfl_xor_sync(0xffffffffu, t2, o);
        if (tid == 0) red[0] = t2;
    }
    __syncthreads();
    float inv = 32.0f / fmaxf(sqrtf(red[0]), 1e-12f);
    const float4 gv = ((const float4*)g)[tid];
    float4 o4;
    o4.x = xv.x * inv * (gv.x + 1.f);
    o4.y = xv.y * inv * (gv.y + 1.f);
    o4.z = xv.z * inv * (gv.z + 1.f);
    o4.w = xv.w * inv * (gv.w + 1.f);
    ((float4*)(out + (size_t)row * Dq))[tid] = o4;
}

// ---------------- fused rmsnorm + causal dwconv(K=3) + bias -> g_y ----------------
__global__ __launch_bounds__(256) void rmsnorm_dwconv_k(const float* __restrict__ x,
                                                        const float* __restrict__ g,
                                                        const float* __restrict__ wdw,
                                                        const float* __restrict__ bdw)
{
    const int row = blockIdx.x;
    const int tid = threadIdx.x;
    const int l = row % Lq;

    float4 xv0 = ((const float4*)(x + (size_t)row * Dq))[tid];
    float4 xv1 = make_float4(0.f,0.f,0.f,0.f);
    float4 xv2 = make_float4(0.f,0.f,0.f,0.f);
    if (l >= 1) xv1 = ((const float4*)(x + (size_t)(row-1) * Dq))[tid];
    if (l >= 2) xv2 = ((const float4*)(x + (size_t)(row-2) * Dq))[tid];

    float s0 = xv0.x*xv0.x + xv0.y*xv0.y + xv0.z*xv0.z + xv0.w*xv0.w;
    float s1 = xv1.x*xv1.x + xv1.y*xv1.y + xv1.z*xv1.z + xv1.w*xv1.w;
    float s2 = xv2.x*xv2.x + xv2.y*xv2.y + xv2.z*xv2.z + xv2.w*xv2.w;
    #pragma unroll
    for (int o = 16; o > 0; o >>= 1) {
        s0 += __shfl_xor_sync(0xffffffffu, s0, o);
        s1 += __shfl_xor_sync(0xffffffffu, s1, o);
        s2 += __shfl_xor_sync(0xffffffffu, s2, o);
    }
    __shared__ float red0[8], red1[8], red2[8], invs[3];
    if ((tid & 31) == 0) { red0[tid>>5]=s0; red1[tid>>5]=s1; red2[tid>>5]=s2; }
    __syncthreads();
    if (tid < 32) {
        float t0 = (tid < 8) ? red0[tid] : 0.f;
        float t1 = (tid < 8) ? red1[tid] : 0.f;
        float t2 = (tid < 8) ? red2[tid] : 0.f;
        #pragma unroll
        for (int o = 4; o > 0; o >>= 1) {
            t0 += __shfl_xor_sync(0xffffffffu, t0, o);
            t1 += __shfl_xor_sync(0xffffffffu, t1, o);
            t2 += __shfl_xor_sync(0xffffffffu, t2, o);
        }
        if (tid == 0) {
            invs[0] = 32.0f / fmaxf(sqrtf(t0), 1e-12f);
            invs[1] = 32.0f / fmaxf(sqrtf(t1), 1e-12f);
            invs[2] = 32.0f / fmaxf(sqrtf(t2), 1e-12f);
        }
    }
    __syncthreads();
    const float inv0 = invs[0], inv1 = invs[1], inv2 = invs[2];
    const float4 gv = ((const float4*)g)[tid];
    const float4* wp = (const float4*)(wdw + tid*12);   // 4 channels x 3 taps
    float4 w4a = wp[0], w4b = wp[1], w4c = wp[2];
    const float4 bd = ((const float4*)bdw)[tid];
    // channel j taps: w0 = tap0, w1 = tap1, w2 = tap2
    float4 y;
    y.x = bd.x + w4a.z*(xv0.x*inv0*(gv.x+1.f)) + w4a.y*(xv1.x*inv1*(gv.x+1.f)) + w4a.x*(xv2.x*inv2*(gv.x+1.f));
    y.y = bd.y + w4b.y*(xv0.y*inv0*(gv.y+1.f)) + w4b.x*(xv1.y*inv1*(gv.y+1.f)) + w4a.w*(xv2.y*inv2*(gv.y+1.f));
    y.z = bd.z + w4c.x*(xv0.z*inv0*(gv.z+1.f)) + w4b.w*(xv1.z*inv1*(gv.z+1.f)) + w4b.z*(xv2.z*inv2*(gv.z+1.f));
    y.w = bd.w + w4c.w*(xv0.w*inv0*(gv.w+1.f)) + w4c.z*(xv1.w*inv1*(gv.w+1.f)) + w4c.y*(xv2.w*inv2*(gv.w+1.f));
    ((float4*)(g_y + (size_t)row * Dq))[tid] = y;
}

// ---------------- fp16 tensor-core NT GEMM (fp32 accum), 2-stage pipeline ----------------
// C[M,N] = A[M,K] * B[N,K]^T ; m16n8k16 fragments stored in frag order.
// MODE 0/3: +bias +res ; MODE 1: plain ; MODE 2: +bias exact gelu
__device__ __forceinline__ uint32_t f32x2_h2(float lo, float hi) {
    uint32_t r;
    asm("cvt.rn.f16x2.f32 %0, %1, %2;" : "=r"(r) : "f"(hi), "f"(lo));
    return r;
}
__device__ __forceinline__ void mma_f16(float* c, const uint32_t* a, const uint32_t* b) {
    asm volatile(
        "mma.sync.aligned.m16n8k16.row.col.f32.f16.f16.f32 "
        "{%0,%1,%2,%3}, {%4,%5,%6,%7}, {%8,%9}, {%0,%1,%2,%3};"
        : "+f"(c[0]), "+f"(c[1]), "+f"(c[2]), "+f"(c[3])
        : "r"(a[0]), "r"(a[1]), "r"(a[2]), "r"(a[3]), "r"(b[0]), "r"(b[1]));
}

template<int MODE>
__global__ __launch_bounds__(256) void gemm_tc(
    const float* __restrict__ A, const float* __restrict__ Bm,
    const float* __restrict__ bias, const float* __restrict__ res,
    float* __restrict__ C, int N_, int K_)
{
    __shared__ __align__(16) uint32_t As[2][2048];   // 128 x 32 f16 frag order
    __shared__ __align__(16) uint32_t Bs[2][2048];

    const int tid  = threadIdx.x;
    const int lane = tid & 31;
    const int g    = lane >> 2;
    const int t    = lane & 3;
    const int wid  = tid >> 5;
    const int wm4  = (wid >> 2) * 4;
    const int wn4  = (wid & 3) * 4;
    const int bm   = blockIdx.y * 128;
    const int bn   = blockIdx.x * 128;

    const int lrow = tid >> 3;
    const int lkc  = (tid & 7) << 2;
    const int kk_s  = lkc >> 4;
    const int kin   = lkc & 15;
    const int khi_s = kin >> 3;
    const int tb_s  = (kin & 7) >> 1;

    // precompute store bases (stage-independent)
    int abase_[4], bbase_[4];
    #pragma unroll
    for (int p = 0; p < 4; p++) {
        int row  = p*32 + lrow;
        int mrow = row >> 4;
        int ri   = row & 15;
        abase_[p] = ((mrow*2 + kk_s)*8 + (ri & 7))*16 + ((ri >> 3) + khi_s*2);
        bbase_[p] = (((row >> 3)*2 + kk_s)*8 + (row & 7))*8 + khi_s;
    }
    const int tpa0 = ((tb_s  ) ^ kk_s)*4, tpa1 = ((tb_s+1) ^ kk_s)*4;
    const int tpb0 = ((tb_s  ) ^ kk_s)*2, tpb1 = ((tb_s+1) ^ kk_s)*2;

    float acc[4][4][4];
    #pragma unroll
    for (int mi = 0; mi < 4; mi++)
        #pragma unroll
        for (int ni = 0; ni < 4; ni++)
            #pragma unroll
            for (int r = 0; r < 4; r++) acc[mi][ni][r] = 0.f;

    float4 pa[4], pb[4];
    const int niter = K_ >> 5;

    // preload iter 0 -> regs -> stage 0
    #pragma unroll
    for (int p = 0; p < 4; p++) {
        int row = p*32 + lrow;
        pa[p] = *(const float4*)(A  + (size_t)(bm + row) * K_ + lkc);
        pb[p] = *(const float4*)(Bm + (size_t)(bn + row) * K_ + lkc);
    }
    #pragma unroll
    for (int p = 0; p < 4; p++) {
        As[0][abase_[p] + tpa0] = f32x2_h2(pa[p].x, pa[p].y);
        As[0][abase_[p] + tpa1] = f32x2_h2(pa[p].z, pa[p].w);
        Bs[0][bbase_[p] + tpb0] = f32x2_h2(pb[p].x, pb[p].y);
        Bs[0][bbase_[p] + tpb1] = f32x2_h2(pb[p].z, pb[p].w);
    }
    // preload iter 1 -> regs
    if (niter > 1) {
        #pragma unroll
        for (int p = 0; p < 4; p++) {
            int row = p*32 + lrow;
            pa[p] = *(const float4*)(A  + (size_t)(bm + row) * K_ + 32 + lkc);
            pb[p] = *(const float4*)(Bm + (size_t)(bn + row) * K_ + 32 + lkc);
        }
    }
    __syncthreads();

    for (int it = 0; it < niter; it++) {
        const int s = it & 1;
        // store regs (data for it+1) into stage s^1; safe: consumed in it-1, synced
        if (it + 1 < niter) {
            #pragma unroll
            for (int p = 0; p < 4; p++) {
                As[s^1][abase_[p] + tpa0] = f32x2_h2(pa[p].x, pa[p].y);
                As[s^1][abase_[p] + tpa1] = f32x2_h2(pa[p].z, pa[p].w);
                Bs[s^1][bbase_[p] + tpb0] = f32x2_h2(pb[p].x, pb[p].y);
                Bs[s^1][bbase_[p] + tpb1] = f32x2_h2(pb[p].z, pb[p].w);
            }
        }
        // issue LDG for it+2
        if (it + 2 < niter) {
            int k0 = (it + 2) << 5;
            #pragma unroll
            for (int p = 0; p < 4; p++) {
                int row = p*32 + lrow;
                pa[p] = *(const float4*)(A  + (size_t)(bm + row) * K_ + k0 + lkc);
                pb[p] = *(const float4*)(Bm + (size_t)(bn + row) * K_ + k0 + lkc);
            }
        }
        // compute from stage s
        #pragma unroll
        for (int kk = 0; kk < 2; kk++) {
            const int tp = t ^ kk;
            uint4 af[4];
            #pragma unroll
            for (int mi = 0; mi < 4; mi++)
                af[mi] = *(const uint4*)&As[s][(((wm4 + mi)*2 + kk)*8 + g)*16 + tp*4];
            uint2 bf[4];
            #pragma unroll
            for (int ni = 0; ni < 4; ni++)
                bf[ni] = *(const uint2*)&Bs[s][(((wn4 + ni)*2 + kk)*8 + g)*8 + tp*2];
            #pragma unroll
            for (int mi = 0; mi < 4; mi++)
                #pragma unroll
                for (int ni = 0; ni < 4; ni++)
                    mma_f16(acc[mi][ni], (const uint32_t*)&af[mi], (const uint32_t*)&bf[ni]);
        }
        __syncthreads();
    }

    // ---------------- epilogue ----------------
    #pragma unroll
    for (int mi = 0; mi < 4; mi++) {
        #pragma unroll
        for (int ni = 0; ni < 4; ni++) {
            int row0 = bm + (wm4 + mi)*16 + g;
            int col  = bn + (wn4 + ni)*8 + 2*t;
            #pragma unroll
            for (int h = 0; h < 2; h++) {
                int row = row0 + h*8;
                float v0 = acc[mi][ni][2*h + 0];
                float v1 = acc[mi][ni][2*h + 1];
                if (MODE == 0 || MODE == 3) {
                    v0 += bias[col]   + res[(size_t)row * N_ + col];
                    v1 += bias[col+1] + res[(size_t)row * N_ + col + 1];
                } else if (MODE == 2) {
                    v0 += bias[col];
                    v1 += bias[col+1];
                    v0 = 0.5f * v0 * (1.f + erff(v0 * 0.70710678118654752f));
                    v1 = 0.5f * v1 * (1.f + erff(v1 * 0.70710678118654752f));
                }
                *(float2*)(C + (size_t)row * N_ + col) = make_float2(v0, v1);
            }
        }
    }
}

// ---------------- minGRU chunked scan ----------------
__global__ __launch_bounds__(256) void scan1_k(const float* __restrict__ hg)
{
    int d  = blockIdx.x * 256 + threadIdx.x;
    int ch = blockIdx.y;
    int b  = blockIdx.z;
    size_t row0 = (size_t)b * Lq + (size_t)ch * CHUNK;
    float h = 0.f, cp = 1.f;
    for (int t = 0; t < CHUNK; t++) {
        size_t r = row0 + t;
        float hd = hg[r*2*Dq + d];
        float gg = hg[r*2*Dq + Dq + d];
        float sp = fmaxf(gg, 0.f) + log1pf(expf(-fabsf(gg)));
        float lg = (hd >= 0.f) ? logf(hd + 0.5f) : (hd - log1pf(expf(hd)));
        float c = expf(-sp);
        float v = expf(gg - sp + lg);
        g_c[r*Dq + d] = c;
        g_v[r*Dq + d] = v;
        h = fmaf(c, h, v);
        cp *= c;
    }
    int sidx = (b*NCHUNK + ch)*Dq + d;
    g_Hc[sidx] = h;
    g_Cc[sidx] = cp;
}

__global__ __launch_bounds__(256) void scan2_k()
{
    int d = blockIdx.x * 256 + threadIdx.x;
    int b = blockIdx.z;
    float h = 0.f;
    for (int ch = 0; ch < NCHUNK; ch++) {
        int sidx = (b*NCHUNK + ch)*Dq + d;
        g_Hi[sidx] = h;
        h = fmaf(g_Cc[sidx], h, g_Hc[sidx]);
    }
}

__global__ __launch_bounds__(256) void scan3_k(const float* __restrict__ x1,
                                               float* __restrict__ x2,
                                               float* __restrict__ nh)
{
    int d  = blockIdx.x * 256 + threadIdx.x;
    int ch = blockIdx.y;
    int b  = blockIdx.z;
    size_t row0 = (size_t)b * Lq + (size_t)ch * CHUNK;
    float h = g_Hi[(b*NCHUNK + ch)*Dq + d];
    for (int t = 0; t < CHUNK; t++) {
        size_t r = row0 + t;
        h = fmaf(g_c[r*Dq + d], h, g_v[r*Dq + d]);
        x2[r*Dq + d] = h + x1[r*Dq + d];
    }
    if (ch == NCHUNK - 1) nh[b*Dq + d] = h;
}

// ---------------- launch ----------------
extern "C" void kernel_launch(void* const* d_in, const int* in_sizes, int n_in,
                              void* d_out, int out_size)
{
    const float* x           = (const float*)d_in[0];
    const float* conv_dw_w   = (const float*)d_in[1];
    const float* conv_dw_b   = (const float*)d_in[2];
    const float* conv_pw_w   = (const float*)d_in[3];
    const float* conv_pw_b   = (const float*)d_in[4];
    const float* conv_norm_g = (const float*)d_in[5];
    const float* gru_norm_g  = (const float*)d_in[6];
    const float* gru_w       = (const float*)d_in[7];
    const float* ff_norm_g   = (const float*)d_in[8];
    const float* ff_w1       = (const float*)d_in[9];
    const float* ff_b1       = (const float*)d_in[10];
    const float* ff_w2       = (const float*)d_in[11];
    const float* ff_b2       = (const float*)d_in[12];
    float* out = (float*)d_out;

    float *xn, *y, *x1, *x2, *hg, *h4;
    cudaGetSymbolAddress((void**)&xn, g_xn);
    cudaGetSymbolAddress((void**)&y,  g_y);
    cudaGetSymbolAddress((void**)&x1, g_x1);
    cudaGetSymbolAddress((void**)&x2, g_x2);
    cudaGetSymbolAddress((void**)&hg, g_hg);
    cudaGetSymbolAddress((void**)&h4, g_h4);

    // 1) conv block (fused rmsnorm+dwconv)
    rmsnorm_dwconv_k<<<Mq, 256>>>(x, conv_norm_g, conv_dw_w, conv_dw_b);
    gemm_tc<0><<<dim3(Dq/128, Mq/128), 256>>>(y, conv_pw_w, conv_pw_b, x, x1, Dq, Dq);

    // 2) gru block
    rmsnorm_k<<<Mq, 256>>>(x1, gru_norm_g, xn);
    gemm_tc<1><<<dim3(2*Dq/128, Mq/128), 256>>>(xn, gru_w, nullptr, nullptr, hg, 2*Dq, Dq);
    scan1_k<<<dim3(Dq/256, NCHUNK, Bq), 256>>>(hg);
    scan2_k<<<dim3(Dq/256, 1, Bq), 256>>>();
    scan3_k<<<dim3(Dq/256, NCHUNK, Bq), 256>>>(x1, x2, out + (size_t)Mq*Dq);

    // 3) ff block
    rmsnorm_k<<<Mq, 256>>>(x2, ff_norm_g, xn);
    gemm_tc<2><<<dim3(4*Dq/128, Mq/128), 256>>>(xn, ff_w1, ff_b1, nullptr, h4, 4*Dq, Dq);
    gemm_tc<3><<<dim3(Dq/128, Mq/128), 256>>>(h4, ff_w2, ff_b2, x2, out, Dq, 4*Dq);
}